// round 15
// baseline (speedup 1.0000x reference)
#include <cuda_runtime.h>
#include <cuda_fp16.h>
#include <mma.h>
#include <math.h>
#include <stdint.h>

using namespace nvcuda;

// Problem constants
#define CHUNKS     8
#define CSIZE      512
#define DIM        4096
#define NROWS      16384
#define INV_TEMP   (1.0f / 0.15f)
#define SINK_ITERS 5

#define NB          8
#define SINK_BLOCKS (CHUNKS * NB)         // 64

// Scratch (device globals — no runtime allocation allowed)
__device__ float    g_r[CHUNKS * CSIZE];              // row offsets
__device__ float    g_c[CHUNKS * CSIZE];              // col offsets
__device__ float    g_mu[CHUNKS * CSIZE];             // Q row means
__device__ unsigned g_barc[CHUNKS];                   // barrier arrive counters
__device__ unsigned g_barg[CHUNKS];                   // barrier generations
__device__ __half   g_eh[CHUNKS * CSIZE * CSIZE];     // 4 MB   Ê = 512(Q-mu) fp16
__device__ __half   g_yh[(size_t)NROWS * DIM];        // 128 MB Y fp16
__device__ float    g_s[(size_t)NROWS * CHUNKS];      // 512 KB row-chunk sums

// ---------------------------------------------------------------------------
// Per-chunk inter-block barrier (generation-counting).
// ---------------------------------------------------------------------------
__device__ __forceinline__ void chunk_barrier(int chunk, unsigned* sgen) {
    __syncthreads();
    if (threadIdx.x == 0) {
        __threadfence();
        unsigned g = *sgen;
        if (atomicAdd(&g_barc[chunk], 1) == NB - 1) {
            g_barc[chunk] = 0;
            __threadfence();
            atomicExch(&g_barg[chunk], g + 1);
        } else {
            while (atomicAdd(&g_barg[chunk], 0) <= g) __nanosleep(64);
        }
        *sgen = g + 1;
    }
    __syncthreads();
}

// ---------------------------------------------------------------------------
// Fused pre-GEMM kernel.
//   blocks [0, 64):  persistent intra-sinkhorn; emits mu and Ê=512(Q-mu) fp16.
//   blocks [64, ..): in-block 8x8 chunk-perm sinkhorn, streaming mix -> yh,
//                    plus fp32 row-chunk sums S[m*8+c].
// ---------------------------------------------------------------------------
__global__ __launch_bounds__(512, 2)
void fused_pre_kernel(const float* __restrict__ intra,
                      const float* __restrict__ x,
                      const float* __restrict__ chunkL,
                      __half* __restrict__ eh,
                      __half* __restrict__ yh,
                      float* __restrict__ S,
                      float* __restrict__ muv,
                      float* __restrict__ rg_, float* __restrict__ cg_) {
    __shared__ float smem[512];
    __shared__ float ws2[16][8];
    __shared__ unsigned sgen;

    if (blockIdx.x < SINK_BLOCKS) {
        // ------------------ intra-sinkhorn lane ------------------
        const int chunk = blockIdx.x >> 3;
        const int sub   = blockIdx.x & 7;
        const int tid   = threadIdx.x;
        const int warp  = tid >> 5;
        const int lane  = tid & 31;
        const float* L = intra + (size_t)chunk * CSIZE * CSIZE;
        float* rv = rg_ + chunk * CSIZE;
        float* cv = cg_ + chunk * CSIZE;

        if (tid == 0) sgen = atomicAdd(&g_barg[chunk], 0);
        __syncthreads();

        for (int it = 0; it < SINK_ITERS; ++it) {
            // r-pass: rows [sub*64, +64), 4 rows per warp
            #pragma unroll
            for (int k = 0; k < 4; ++k) {
                int row = sub * 64 + warp * 4 + k;
                const float4* lp = (const float4*)(L + (size_t)row * CSIZE);
                float s = 0.0f;
                #pragma unroll
                for (int q = 0; q < 4; ++q) {
                    float4 t = lp[lane + q * 32];
                    if (it > 0) {
                        float4 cc = ((const float4*)cv)[lane + q * 32];
                        s += __expf(t.x * INV_TEMP - cc.x)
                           + __expf(t.y * INV_TEMP - cc.y)
                           + __expf(t.z * INV_TEMP - cc.z)
                           + __expf(t.w * INV_TEMP - cc.w);
                    } else {
                        s += __expf(t.x * INV_TEMP) + __expf(t.y * INV_TEMP)
                           + __expf(t.z * INV_TEMP) + __expf(t.w * INV_TEMP);
                    }
                }
                #pragma unroll
                for (int o = 16; o > 0; o >>= 1)
                    s += __shfl_xor_sync(0xFFFFFFFFu, s, o);
                if (lane == 0) rv[row] = __logf(s);
            }
            chunk_barrier(chunk, &sgen);

            // c-pass: cols [sub*64, +64)
            {
                int col = sub * 64 + (tid & 63);
                int rgp = tid >> 6;
                float s = 0.0f;
                for (int row = rgp; row < CSIZE; row += 8)
                    s += __expf(L[(size_t)row * CSIZE + col] * INV_TEMP - rv[row]);
                smem[tid] = s;
                __syncthreads();
                if (tid < 64) {
                    float tot = smem[tid];
                    #pragma unroll
                    for (int j = 1; j < 8; ++j) tot += smem[tid + j * 64];
                    cv[sub * 64 + tid] = __logf(tot);
                }
                __syncthreads();
            }
            chunk_barrier(chunk, &sgen);
        }

        // extra sweep: 512*mu_i = (sum_j exp(L*invT - c_j)) * exp(-r_i)
        #pragma unroll
        for (int k = 0; k < 4; ++k) {
            int row = sub * 64 + warp * 4 + k;
            const float4* lp = (const float4*)(L + (size_t)row * CSIZE);
            float s = 0.0f;
            #pragma unroll
            for (int q = 0; q < 4; ++q) {
                float4 t = lp[lane + q * 32];
                float4 cc = ((const float4*)cv)[lane + q * 32];
                s += __expf(t.x * INV_TEMP - cc.x)
                   + __expf(t.y * INV_TEMP - cc.y)
                   + __expf(t.z * INV_TEMP - cc.z)
                   + __expf(t.w * INV_TEMP - cc.w);
            }
            #pragma unroll
            for (int o = 16; o > 0; o >>= 1)
                s += __shfl_xor_sync(0xFFFFFFFFu, s, o);
            if (lane == 0) {
                float m512 = s * __expf(-rv[row]);
                smem[row - sub * 64] = m512;                 // 512*mu
                muv[chunk * CSIZE + row] = m512 * (1.0f / 512.0f);
            }
        }
        __syncthreads();

        // emit Ê = 512*q - 512*mu, rows [sub*64, +64)
        float cj = cv[tid];
        __half* ebase = eh + (size_t)chunk * CSIZE * CSIZE;
        for (int row = sub * 64; row < sub * 64 + 64; ++row) {
            float rr = rv[row];
            float m512 = smem[row - sub * 64];
            float q512 = 512.0f * __expf(L[(size_t)row * CSIZE + tid] * INV_TEMP
                                         - rr - cj);
            ebase[(size_t)row * CSIZE + tid] = __float2half(q512 - m512);
        }
    } else {
        // ------------------ chunk-mix lane ------------------
        const int t = threadIdx.x;
        const int warp = t >> 5;
        const int lane = t & 31;
        float v = 0.0f;
        const int pr = t >> 3, pc = t & 7;
        if (t < 64) v = chunkL[t] * INV_TEMP;

        for (int it = 0; it < SINK_ITERS; ++it) {
            if (t < 64) smem[t] = v;
            __syncthreads();
            if (t < 64) {
                float mx = -1e30f;
                #pragma unroll
                for (int j = 0; j < 8; ++j) mx = fmaxf(mx, smem[pr * 8 + j]);
                float sm = 0.0f;
                #pragma unroll
                for (int j = 0; j < 8; ++j) sm += expf(smem[pr * 8 + j] - mx);
                v -= mx + logf(sm);
            }
            __syncthreads();
            if (t < 64) smem[t] = v;
            __syncthreads();
            if (t < 64) {
                float mx = -1e30f;
                #pragma unroll
                for (int j = 0; j < 8; ++j) mx = fmaxf(mx, smem[j * 8 + pc]);
                float sm = 0.0f;
                #pragma unroll
                for (int j = 0; j < 8; ++j) sm += expf(smem[j * 8 + pc] - mx);
                v -= mx + logf(sm);
            }
            __syncthreads();
        }
        if (t < 64) smem[t] = expf(v);     // P in smem[0..63]
        __syncthreads();

        int id = (blockIdx.x - SINK_BLOCKS) * 512 + t;
        int b  = id >> 7;
        int d4 = id & 127;

        const float4* xb = (const float4*)(x + (size_t)b * DIM) + d4;

        float4 xv[8];
        #pragma unroll
        for (int j = 0; j < 8; ++j) xv[j] = __ldcs(xb + (size_t)j * 128);

        float srow[8];
        #pragma unroll
        for (int i = 0; i < 8; ++i) {
            float4 acc = make_float4(0.f, 0.f, 0.f, 0.f);
            #pragma unroll
            for (int j = 0; j < 8; ++j) {
                float w = smem[i * 8 + j];
                acc.x += w * xv[j].x;
                acc.y += w * xv[j].y;
                acc.z += w * xv[j].z;
                acc.w += w * xv[j].w;
            }
            srow[i] = acc.x + acc.y + acc.z + acc.w;
            __half2 h01 = __floats2half2_rn(acc.x, acc.y);
            __half2 h23 = __floats2half2_rn(acc.z, acc.w);
            size_t e = (size_t)b * DIM + (size_t)i * CSIZE + (size_t)d4 * 4;
            __stcs(((__half2*)yh) + (e >> 1),       h01);
            __stcs(((__half2*)yh) + (e >> 1) + 1,   h23);
        }

        // S[m, c]: reduce srow over the 128 lanes (4 warps) of each row
        #pragma unroll
        for (int i = 0; i < 8; ++i) {
            float vv = srow[i];
            #pragma unroll
            for (int off = 16; off > 0; off >>= 1)
                vv += __shfl_down_sync(0xFFFFFFFFu, vv, off);
            if (lane == 0) ws2[warp][i] = vv;
        }
        __syncthreads();
        if (t < 32) {
            int rsel  = t >> 3;             // 0..3: row within block
            int chunk = t & 7;
            float vv = ws2[rsel * 4 + 0][chunk] + ws2[rsel * 4 + 1][chunk]
                     + ws2[rsel * 4 + 2][chunk] + ws2[rsel * 4 + 3][chunk];
            int brow = (blockIdx.x - SINK_BLOCKS) * 4 + rsel;
            S[(size_t)brow * 8 + chunk] = vv;
        }
    }
}

// ---------------------------------------------------------------------------
// WMMA GEMM with fp16 accumulators (ncu: fp32-acc HMMA ran at 47% of pipe
// peak -> fp16-acc should be ~2x). Z = Y @ Ê^T; epilogue:
// out = Z/512 + mu_n * S[m,c]. CTA 128x128, 4-stage cp.async ring, 1 sync/iter.
// ---------------------------------------------------------------------------
#define LDS_PAD 40
#define NKITER  16
#define NSTAGE  4
#define MAT_ELEMS (128 * LDS_PAD)
#define STAGE_ELEMS (2 * MAT_ELEMS)
#define GEMM_SMEM (NSTAGE * STAGE_ELEMS * 2)  // 81920 bytes
#define EPI_LD  40                            // 8 warps * 64*40 halfs = 40960 B

__device__ __forceinline__ void cp16(uint32_t dst, const void* src) {
    asm volatile("cp.async.cg.shared.global [%0], [%1], 16;" :: "r"(dst), "l"(src));
}

__global__ __launch_bounds__(256, 2)
void wmma_gemm_kernel(const __half* __restrict__ yh,
                      const __half* __restrict__ eh,
                      const float* __restrict__ mu,
                      const float* __restrict__ S,
                      float* __restrict__ out) {
    extern __shared__ __half smem[];

    const int c  = blockIdx.z;
    const int m0 = blockIdx.y * 128;
    const int n0 = blockIdx.x * 128;
    const int tid = threadIdx.x;
    const int wid = tid >> 5;
    const int lane = tid & 31;
    const int wm  = wid & 1;
    const int wn  = wid >> 1;

    wmma::fragment<wmma::accumulator, 16, 16, 16, __half> acc[4][2];
    #pragma unroll
    for (int i = 0; i < 4; ++i)
        #pragma unroll
        for (int j = 0; j < 2; ++j)
            wmma::fill_fragment(acc[i][j], __float2half(0.0f));

    const int r0  = (tid + 0)   >> 2;
    const int cb0 = (tid + 0)   & 3;
    const int r1  = (tid + 256) >> 2;
    const int cb1 = (tid + 256) & 3;

    uint32_t aD0[NSTAGE], aD1[NSTAGE], bD0[NSTAGE], bD1[NSTAGE];
    #pragma unroll
    for (int s = 0; s < NSTAGE; ++s) {
        __half* sA = smem + s * STAGE_ELEMS;
        __half* sB = sA + MAT_ELEMS;
        aD0[s] = (uint32_t)__cvta_generic_to_shared(sA + r0 * LDS_PAD + cb0 * 8);
        aD1[s] = (uint32_t)__cvta_generic_to_shared(sA + r1 * LDS_PAD + cb1 * 8);
        bD0[s] = (uint32_t)__cvta_generic_to_shared(sB + r0 * LDS_PAD + cb0 * 8);
        bD1[s] = (uint32_t)__cvta_generic_to_shared(sB + r1 * LDS_PAD + cb1 * 8);
    }

    const __half* Abase = yh + (size_t)m0 * DIM + (size_t)c * CSIZE;
    const __half* Bbase = eh + (size_t)c * CSIZE * CSIZE + (size_t)n0 * CSIZE;

    auto issue_loads = [&](int i, int st) {
        int kk = i << 5;
        const __half* A = Abase + kk;
        const __half* B = Bbase + kk;
        cp16(aD0[st], A + (size_t)r0 * DIM + cb0 * 8);
        cp16(aD1[st], A + (size_t)r1 * DIM + cb1 * 8);
        cp16(bD0[st], B + (size_t)r0 * CSIZE + cb0 * 8);
        cp16(bD1[st], B + (size_t)r1 * CSIZE + cb1 * 8);
        asm volatile("cp.async.commit_group;" ::: "memory");
    };

    issue_loads(0, 0);
    issue_loads(1, 1);
    issue_loads(2, 2);

    for (int i = 0; i < NKITER; ++i) {
        const int st = i & 3;

        if (i + 2 < NKITER)
            asm volatile("cp.async.wait_group 2;" ::: "memory");
        else if (i + 2 == NKITER)
            asm volatile("cp.async.wait_group 1;" ::: "memory");
        else
            asm volatile("cp.async.wait_group 0;" ::: "memory");
        __syncthreads();

        if (i + 3 < NKITER) issue_loads(i + 3, (i + 3) & 3);

        const __half* As = smem + st * STAGE_ELEMS;
        const __half* Bs = As + MAT_ELEMS;

        #pragma unroll
        for (int k2 = 0; k2 < 2; ++k2) {
            wmma::fragment<wmma::matrix_a, 16, 16, 16, __half, wmma::row_major> af[4];
            wmma::fragment<wmma::matrix_b, 16, 16, 16, __half, wmma::col_major> bf[2];
            #pragma unroll
            for (int mi = 0; mi < 4; ++mi)
                wmma::load_matrix_sync(af[mi],
                    &As[(wm * 64 + mi * 16) * LDS_PAD + k2 * 16], LDS_PAD);
            #pragma unroll
            for (int nj = 0; nj < 2; ++nj)
                wmma::load_matrix_sync(bf[nj],
                    &Bs[(wn * 32 + nj * 16) * LDS_PAD + k2 * 16], LDS_PAD);
            #pragma unroll
            for (int mi = 0; mi < 4; ++mi)
                #pragma unroll
                for (int nj = 0; nj < 2; ++nj)
                    wmma::mma_sync(acc[mi][nj], af[mi], bf[nj], acc[mi][nj]);
        }
    }

    // Epilogue: roundtrip through smem, apply out = Z/512 + mu_n * S[m,c].
    __syncthreads();
    __half* scratch = smem + wid * (64 * EPI_LD);
    #pragma unroll
    for (int mi = 0; mi < 4; ++mi)
        #pragma unroll
        for (int nj = 0; nj < 2; ++nj)
            wmma::store_matrix_sync(scratch + (mi * 16) * EPI_LD + nj * 16,
                                    acc[mi][nj], EPI_LD, wmma::mem_row_major);
    __syncwarp();

    const int ncol = n0 + wn * 32 + lane;
    const float mun = mu[c * CSIZE + ncol];
    const float* Sbase = S + (size_t)(m0 + wm * 64) * 8 + c;
    float* obase = out + (size_t)(m0 + wm * 64) * DIM + (size_t)c * CSIZE + ncol;

    #pragma unroll 4
    for (int r = 0; r < 64; ++r) {
        float z = __half2float(scratch[r * EPI_LD + lane]);
        float sv = Sbase[(size_t)r * 8];
        obase[(size_t)r * DIM] = z * (1.0f / 512.0f) + mun * sv;
    }
}

// ---------------------------------------------------------------------------
// Launch
// ---------------------------------------------------------------------------
extern "C" void kernel_launch(void* const* d_in, const int* in_sizes, int n_in,
                              void* d_out, int out_size) {
    const float* x            = (const float*)d_in[0];
    const float* chunk_logits = (const float*)d_in[1];
    const float* intra_logits = (const float*)d_in[2];
    float*       out          = (float*)d_out;

    float*  rv; cudaGetSymbolAddress((void**)&rv, g_r);
    float*  cv; cudaGetSymbolAddress((void**)&cv, g_c);
    float*  mu; cudaGetSymbolAddress((void**)&mu, g_mu);
    float*  S;  cudaGetSymbolAddress((void**)&S,  g_s);
    __half* eh; cudaGetSymbolAddress((void**)&eh, g_eh);
    __half* yh; cudaGetSymbolAddress((void**)&yh, g_yh);

    // 1) fused: intra-sinkhorn (mu, Ê) || chunk-perm + mix (yh, S)
    fused_pre_kernel<<<SINK_BLOCKS + (NROWS * 128) / 512, 512>>>(
        intra_logits, x, chunk_logits, eh, yh, S, mu, rv, cv);

    // 2) fp16-accum GEMM + rank-1 epilogue
    cudaFuncSetAttribute(wmma_gemm_kernel,
                         cudaFuncAttributeMaxDynamicSharedMemorySize, GEMM_SMEM);
    dim3 grid(4, NROWS / 128, CHUNKS);
    wmma_gemm_kernel<<<grid, 256, GEMM_SMEM>>>(yh, eh, mu, S, out);
}

// round 16
// speedup vs baseline: 1.2389x; 1.2389x over previous
#include <cuda_runtime.h>
#include <cuda_fp16.h>
#include <mma.h>
#include <math.h>
#include <stdint.h>

using namespace nvcuda;

// Problem constants
#define CHUNKS     8
#define CSIZE      512
#define DIM        4096
#define NROWS      16384
#define INV_TEMP   (1.0f / 0.15f)
#define SINK_ITERS 5

#define NB          8
#define SINK_BLOCKS (CHUNKS * NB)         // 64

// Scratch (device globals — no runtime allocation allowed)
__device__ float    g_r[CHUNKS * CSIZE];              // row offsets
__device__ float    g_c[CHUNKS * CSIZE];              // col offsets
__device__ unsigned g_barc[CHUNKS];                   // barrier arrive counters
__device__ unsigned g_barg[CHUNKS];                   // barrier generations
__device__ __half   g_qh[CHUNKS * CSIZE * CSIZE];     // 4 MB   Q fp16
__device__ __half   g_yh[(size_t)NROWS * DIM];        // 128 MB Y fp16

// ---------------------------------------------------------------------------
// Per-chunk inter-block barrier (generation-counting).
// ---------------------------------------------------------------------------
__device__ __forceinline__ void chunk_barrier(int chunk, unsigned* sgen) {
    __syncthreads();
    if (threadIdx.x == 0) {
        __threadfence();
        unsigned g = *sgen;
        if (atomicAdd(&g_barc[chunk], 1) == NB - 1) {
            g_barc[chunk] = 0;
            __threadfence();
            atomicExch(&g_barg[chunk], g + 1);
        } else {
            while (atomicAdd(&g_barg[chunk], 0) <= g) __nanosleep(64);
        }
        *sgen = g + 1;
    }
    __syncthreads();
}

// ---------------------------------------------------------------------------
// Fused pre-GEMM kernel (R13/R14 proven version).
//   blocks [0, 64):  persistent intra-sinkhorn -> qh = exp(L - r - c) fp16
//   blocks [64, ..): in-block 8x8 chunk-perm sinkhorn, then streaming mix.
// ---------------------------------------------------------------------------
__global__ __launch_bounds__(512, 2)
void fused_pre_kernel(const float* __restrict__ intra,
                      const float* __restrict__ x,
                      const float* __restrict__ chunkL,
                      __half* __restrict__ qh,
                      __half* __restrict__ yh,
                      float* __restrict__ rg_, float* __restrict__ cg_) {
    __shared__ float smem[512];
    __shared__ unsigned sgen;

    if (blockIdx.x < SINK_BLOCKS) {
        const int chunk = blockIdx.x >> 3;
        const int sub   = blockIdx.x & 7;
        const int tid   = threadIdx.x;
        const int warp  = tid >> 5;
        const int lane  = tid & 31;
        const float* L = intra + (size_t)chunk * CSIZE * CSIZE;
        float* rv = rg_ + chunk * CSIZE;
        float* cv = cg_ + chunk * CSIZE;

        if (tid == 0) sgen = atomicAdd(&g_barg[chunk], 0);
        __syncthreads();

        for (int it = 0; it < SINK_ITERS; ++it) {
            #pragma unroll
            for (int k = 0; k < 4; ++k) {
                int row = sub * 64 + warp * 4 + k;
                const float4* lp = (const float4*)(L + (size_t)row * CSIZE);
                float s = 0.0f;
                #pragma unroll
                for (int q = 0; q < 4; ++q) {
                    float4 t = lp[lane + q * 32];
                    if (it > 0) {
                        float4 cc = ((const float4*)cv)[lane + q * 32];
                        s += __expf(t.x * INV_TEMP - cc.x)
                           + __expf(t.y * INV_TEMP - cc.y)
                           + __expf(t.z * INV_TEMP - cc.z)
                           + __expf(t.w * INV_TEMP - cc.w);
                    } else {
                        s += __expf(t.x * INV_TEMP) + __expf(t.y * INV_TEMP)
                           + __expf(t.z * INV_TEMP) + __expf(t.w * INV_TEMP);
                    }
                }
                #pragma unroll
                for (int o = 16; o > 0; o >>= 1)
                    s += __shfl_xor_sync(0xFFFFFFFFu, s, o);
                if (lane == 0) rv[row] = __logf(s);
            }
            chunk_barrier(chunk, &sgen);

            {
                int col = sub * 64 + (tid & 63);
                int rgp = tid >> 6;
                float s = 0.0f;
                for (int row = rgp; row < CSIZE; row += 8)
                    s += __expf(L[(size_t)row * CSIZE + col] * INV_TEMP - rv[row]);
                smem[tid] = s;
                __syncthreads();
                if (tid < 64) {
                    float tot = smem[tid];
                    #pragma unroll
                    for (int j = 1; j < 8; ++j) tot += smem[tid + j * 64];
                    cv[sub * 64 + tid] = __logf(tot);
                }
                __syncthreads();
            }
            chunk_barrier(chunk, &sgen);
        }

        float cj = cv[tid];
        __half* qbase = qh + (size_t)chunk * CSIZE * CSIZE;
        for (int row = sub * 64; row < sub * 64 + 64; ++row) {
            float rr = rv[row];
            qbase[(size_t)row * CSIZE + tid] = __float2half(
                __expf(L[(size_t)row * CSIZE + tid] * INV_TEMP - rr - cj));
        }
    } else {
        const int t = threadIdx.x;
        float v = 0.0f;
        const int pr = t >> 3, pc = t & 7;
        if (t < 64) v = chunkL[t] * INV_TEMP;

        for (int it = 0; it < SINK_ITERS; ++it) {
            if (t < 64) smem[t] = v;
            __syncthreads();
            if (t < 64) {
                float mx = -1e30f;
                #pragma unroll
                for (int j = 0; j < 8; ++j) mx = fmaxf(mx, smem[pr * 8 + j]);
                float sm = 0.0f;
                #pragma unroll
                for (int j = 0; j < 8; ++j) sm += expf(smem[pr * 8 + j] - mx);
                v -= mx + logf(sm);
            }
            __syncthreads();
            if (t < 64) smem[t] = v;
            __syncthreads();
            if (t < 64) {
                float mx = -1e30f;
                #pragma unroll
                for (int j = 0; j < 8; ++j) mx = fmaxf(mx, smem[j * 8 + pc]);
                float sm = 0.0f;
                #pragma unroll
                for (int j = 0; j < 8; ++j) sm += expf(smem[j * 8 + pc] - mx);
                v -= mx + logf(sm);
            }
            __syncthreads();
        }
        if (t < 64) smem[t] = expf(v);
        __syncthreads();

        int id = (blockIdx.x - SINK_BLOCKS) * 512 + t;
        int b  = id >> 7;
        int d4 = id & 127;

        const float4* xb = (const float4*)(x + (size_t)b * DIM) + d4;

        float4 xv[8];
        #pragma unroll
        for (int j = 0; j < 8; ++j) xv[j] = __ldcs(xb + (size_t)j * 128);

        #pragma unroll
        for (int i = 0; i < 8; ++i) {
            float4 acc = make_float4(0.f, 0.f, 0.f, 0.f);
            #pragma unroll
            for (int j = 0; j < 8; ++j) {
                float w = smem[i * 8 + j];
                acc.x += w * xv[j].x;
                acc.y += w * xv[j].y;
                acc.z += w * xv[j].z;
                acc.w += w * xv[j].w;
            }
            __half2 h01 = __floats2half2_rn(acc.x, acc.y);
            __half2 h23 = __floats2half2_rn(acc.z, acc.w);
            size_t e = (size_t)b * DIM + (size_t)i * CSIZE + (size_t)d4 * 4;
            __stcs(((__half2*)yh) + (e >> 1),       h01);
            __stcs(((__half2*)yh) + (e >> 1) + 1,   h23);
        }
    }
}

// ---------------------------------------------------------------------------
// WMMA GEMM, fp16 in / fp32 accum. CTA 128x128.
// K-step 64 (8 iters instead of 16): halves barrier/wait events — ncu showed
// ~53% tensor-pipe idle dominated by per-iter sync overhead, HMMA work fixed
// at ~115us. 3-stage cp.async ring (1 ahead + 1 landing), 1 sync per iter.
// ---------------------------------------------------------------------------
#define KSTEP   64
#define NKITER  8                         // 512 / 64
#define NSTAGE  3
#define LDS_PAD 72                        // 64 halfs + 8 pad = 144 B row
#define MAT_ELEMS (128 * LDS_PAD)         // 9216 elems per matrix per stage
#define STAGE_ELEMS (2 * MAT_ELEMS)
#define GEMM_SMEM (NSTAGE * STAGE_ELEMS * 2)   // 110592 bytes

__device__ __forceinline__ void cp16(uint32_t dst, const void* src) {
    asm volatile("cp.async.cg.shared.global [%0], [%1], 16;" :: "r"(dst), "l"(src));
}

__global__ __launch_bounds__(256, 2)
void wmma_gemm_kernel(const __half* __restrict__ yh,
                      const __half* __restrict__ qh,
                      float* __restrict__ out) {
    extern __shared__ __half smem[];

    const int c  = blockIdx.z;
    const int m0 = blockIdx.y * 128;
    const int n0 = blockIdx.x * 128;
    const int tid = threadIdx.x;
    const int wid = tid >> 5;
    const int wm  = wid & 1;       // 0..1 -> 64-row slab
    const int wn  = wid >> 1;      // 0..3 -> 32-col slab

    wmma::fragment<wmma::accumulator, 16, 16, 16, float> acc[4][2];
    #pragma unroll
    for (int i = 0; i < 4; ++i)
        #pragma unroll
        for (int j = 0; j < 2; ++j) wmma::fill_fragment(acc[i][j], 0.0f);

    // Load assignment per stage: each matrix = 128 rows x 4 x 16B units
    // = 1024 units; 256 threads -> 4 units per thread per matrix.
    uint32_t aD[NSTAGE][4], bD[NSTAGE][4];
    int gr[4], gc[4];
    #pragma unroll
    for (int u = 0; u < 4; ++u) {
        int unit = tid + u * 256;
        gr[u] = unit >> 3;          // row 0..127
        gc[u] = unit & 7;           // 16B chunk 0..7
    }
    #pragma unroll
    for (int s = 0; s < NSTAGE; ++s) {
        __half* sA = smem + s * STAGE_ELEMS;
        __half* sB = sA + MAT_ELEMS;
        #pragma unroll
        for (int u = 0; u < 4; ++u) {
            aD[s][u] = (uint32_t)__cvta_generic_to_shared(
                           sA + gr[u] * LDS_PAD + gc[u] * 8);
            bD[s][u] = (uint32_t)__cvta_generic_to_shared(
                           sB + gr[u] * LDS_PAD + gc[u] * 8);
        }
    }

    const __half* Abase = yh + (size_t)m0 * DIM + (size_t)c * CSIZE;
    const __half* Bbase = qh + (size_t)c * CSIZE * CSIZE + (size_t)n0 * CSIZE;

    auto issue_loads = [&](int i, int st) {
        int kk = i * KSTEP;
        #pragma unroll
        for (int u = 0; u < 4; ++u) {
            cp16(aD[st][u], Abase + (size_t)gr[u] * DIM   + kk + gc[u] * 8);
            cp16(bD[st][u], Bbase + (size_t)gr[u] * CSIZE + kk + gc[u] * 8);
        }
        asm volatile("cp.async.commit_group;" ::: "memory");
    };

    // prologue: 2 stages in flight
    issue_loads(0, 0);
    issue_loads(1, 1);

    for (int i = 0; i < NKITER; ++i) {
        const int st = i % 3;

        if (i + 1 < NKITER)
            asm volatile("cp.async.wait_group 1;" ::: "memory");
        else
            asm volatile("cp.async.wait_group 0;" ::: "memory");
        __syncthreads();   // single barrier per iter; frees stage (i-1)%3

        if (i + 2 < NKITER) issue_loads(i + 2, (i + 2) % 3);

        const __half* As = smem + st * STAGE_ELEMS;
        const __half* Bs = As + MAT_ELEMS;

        #pragma unroll
        for (int k2 = 0; k2 < 4; ++k2) {
            wmma::fragment<wmma::matrix_a, 16, 16, 16, __half, wmma::row_major> af[4];
            wmma::fragment<wmma::matrix_b, 16, 16, 16, __half, wmma::col_major> bf[2];
            #pragma unroll
            for (int mi = 0; mi < 4; ++mi)
                wmma::load_matrix_sync(af[mi],
                    &As[(wm * 64 + mi * 16) * LDS_PAD + k2 * 16], LDS_PAD);
            #pragma unroll
            for (int nj = 0; nj < 2; ++nj)
                wmma::load_matrix_sync(bf[nj],
                    &Bs[(wn * 32 + nj * 16) * LDS_PAD + k2 * 16], LDS_PAD);
            #pragma unroll
            for (int mi = 0; mi < 4; ++mi)
                #pragma unroll
                for (int nj = 0; nj < 2; ++nj)
                    wmma::mma_sync(acc[mi][nj], af[mi], bf[nj], acc[mi][nj]);
        }
        // no trailing barrier: next iter's post-wait sync provides ordering
    }

    // epilogue: direct store to out
    #pragma unroll
    for (int mi = 0; mi < 4; ++mi) {
        #pragma unroll
        for (int nj = 0; nj < 2; ++nj) {
            float* dst = out + (size_t)(m0 + wm * 64 + mi * 16) * DIM
                             + (size_t)c * CSIZE + n0 + wn * 32 + nj * 16;
            wmma::store_matrix_sync(dst, acc[mi][nj], DIM, wmma::mem_row_major);
        }
    }
}

// ---------------------------------------------------------------------------
// Launch: fused (chunk-perm + intra-sinkhorn || mix) -> GEMM.
// ---------------------------------------------------------------------------
extern "C" void kernel_launch(void* const* d_in, const int* in_sizes, int n_in,
                              void* d_out, int out_size) {
    const float* x            = (const float*)d_in[0];
    const float* chunk_logits = (const float*)d_in[1];
    const float* intra_logits = (const float*)d_in[2];
    float*       out          = (float*)d_out;

    float*  rv; cudaGetSymbolAddress((void**)&rv, g_r);
    float*  cv; cudaGetSymbolAddress((void**)&cv, g_c);
    __half* qh; cudaGetSymbolAddress((void**)&qh, g_qh);
    __half* yh; cudaGetSymbolAddress((void**)&yh, g_yh);

    // 1) fused: intra-sinkhorn (64 persistent blocks) || chunk-perm + mix
    fused_pre_kernel<<<SINK_BLOCKS + (NROWS * 128) / 512, 512>>>(
        intra_logits, x, chunk_logits, qh, yh, rv, cv);

    // 2) tensor-core GEMM, K-step 64, 3-stage ring, 2 CTA/SM
    cudaFuncSetAttribute(wmma_gemm_kernel,
                         cudaFuncAttributeMaxDynamicSharedMemorySize, GEMM_SMEM);
    dim3 grid(4, NROWS / 128, CHUNKS);
    wmma_gemm_kernel<<<grid, 256, GEMM_SMEM>>>(yh, qh, out);
}

// round 17
// speedup vs baseline: 1.2439x; 1.0040x over previous
#include <cuda_runtime.h>
#include <cuda_fp16.h>
#include <mma.h>
#include <math.h>
#include <stdint.h>

using namespace nvcuda;

// Problem constants
#define CHUNKS     8
#define CSIZE      512
#define DIM        4096
#define NROWS      16384
#define INV_TEMP   (1.0f / 0.15f)
#define SINK_ITERS 5

#define NB          8
#define SINK_BLOCKS (CHUNKS * NB)         // 64

// Scratch (device globals — no runtime allocation allowed)
__device__ float    g_r[CHUNKS * CSIZE];              // row offsets
__device__ float    g_c[CHUNKS * CSIZE];              // col offsets
__device__ unsigned g_barc[CHUNKS];                   // barrier arrive counters
__device__ unsigned g_barg[CHUNKS];                   // barrier generations
__device__ __half   g_qh[CHUNKS * CSIZE * CSIZE];     // 4 MB   Q fp16
__device__ __half   g_yh[(size_t)NROWS * DIM];        // 128 MB Y fp16

// ---------------------------------------------------------------------------
// Per-chunk inter-block barrier (generation-counting).
// ---------------------------------------------------------------------------
__device__ __forceinline__ void chunk_barrier(int chunk, unsigned* sgen) {
    __syncthreads();
    if (threadIdx.x == 0) {
        __threadfence();
        unsigned g = *sgen;
        if (atomicAdd(&g_barc[chunk], 1) == NB - 1) {
            g_barc[chunk] = 0;
            __threadfence();
            atomicExch(&g_barg[chunk], g + 1);
        } else {
            while (atomicAdd(&g_barg[chunk], 0) <= g) __nanosleep(64);
        }
        *sgen = g + 1;
    }
    __syncthreads();
}

// ---------------------------------------------------------------------------
// Fused pre-GEMM kernel (proven).
//   blocks [0, 64):  persistent intra-sinkhorn -> qh = exp(L - r - c) fp16
//   blocks [64, ..): in-block 8x8 chunk-perm sinkhorn, then streaming mix.
// ---------------------------------------------------------------------------
__global__ __launch_bounds__(512, 2)
void fused_pre_kernel(const float* __restrict__ intra,
                      const float* __restrict__ x,
                      const float* __restrict__ chunkL,
                      __half* __restrict__ qh,
                      __half* __restrict__ yh,
                      float* __restrict__ rg_, float* __restrict__ cg_) {
    __shared__ float smem[512];
    __shared__ unsigned sgen;

    if (blockIdx.x < SINK_BLOCKS) {
        const int chunk = blockIdx.x >> 3;
        const int sub   = blockIdx.x & 7;
        const int tid   = threadIdx.x;
        const int warp  = tid >> 5;
        const int lane  = tid & 31;
        const float* L = intra + (size_t)chunk * CSIZE * CSIZE;
        float* rv = rg_ + chunk * CSIZE;
        float* cv = cg_ + chunk * CSIZE;

        if (tid == 0) sgen = atomicAdd(&g_barg[chunk], 0);
        __syncthreads();

        for (int it = 0; it < SINK_ITERS; ++it) {
            #pragma unroll
            for (int k = 0; k < 4; ++k) {
                int row = sub * 64 + warp * 4 + k;
                const float4* lp = (const float4*)(L + (size_t)row * CSIZE);
                float s = 0.0f;
                #pragma unroll
                for (int q = 0; q < 4; ++q) {
                    float4 t = lp[lane + q * 32];
                    if (it > 0) {
                        float4 cc = ((const float4*)cv)[lane + q * 32];
                        s += __expf(t.x * INV_TEMP - cc.x)
                           + __expf(t.y * INV_TEMP - cc.y)
                           + __expf(t.z * INV_TEMP - cc.z)
                           + __expf(t.w * INV_TEMP - cc.w);
                    } else {
                        s += __expf(t.x * INV_TEMP) + __expf(t.y * INV_TEMP)
                           + __expf(t.z * INV_TEMP) + __expf(t.w * INV_TEMP);
                    }
                }
                #pragma unroll
                for (int o = 16; o > 0; o >>= 1)
                    s += __shfl_xor_sync(0xFFFFFFFFu, s, o);
                if (lane == 0) rv[row] = __logf(s);
            }
            chunk_barrier(chunk, &sgen);

            {
                int col = sub * 64 + (tid & 63);
                int rgp = tid >> 6;
                float s = 0.0f;
                for (int row = rgp; row < CSIZE; row += 8)
                    s += __expf(L[(size_t)row * CSIZE + col] * INV_TEMP - rv[row]);
                smem[tid] = s;
                __syncthreads();
                if (tid < 64) {
                    float tot = smem[tid];
                    #pragma unroll
                    for (int j = 1; j < 8; ++j) tot += smem[tid + j * 64];
                    cv[sub * 64 + tid] = __logf(tot);
                }
                __syncthreads();
            }
            chunk_barrier(chunk, &sgen);
        }

        float cj = cv[tid];
        __half* qbase = qh + (size_t)chunk * CSIZE * CSIZE;
        for (int row = sub * 64; row < sub * 64 + 64; ++row) {
            float rr = rv[row];
            qbase[(size_t)row * CSIZE + tid] = __float2half(
                __expf(L[(size_t)row * CSIZE + tid] * INV_TEMP - rr - cj));
        }
    } else {
        const int t = threadIdx.x;
        float v = 0.0f;
        const int pr = t >> 3, pc = t & 7;
        if (t < 64) v = chunkL[t] * INV_TEMP;

        for (int it = 0; it < SINK_ITERS; ++it) {
            if (t < 64) smem[t] = v;
            __syncthreads();
            if (t < 64) {
                float mx = -1e30f;
                #pragma unroll
                for (int j = 0; j < 8; ++j) mx = fmaxf(mx, smem[pr * 8 + j]);
                float sm = 0.0f;
                #pragma unroll
                for (int j = 0; j < 8; ++j) sm += expf(smem[pr * 8 + j] - mx);
                v -= mx + logf(sm);
            }
            __syncthreads();
            if (t < 64) smem[t] = v;
            __syncthreads();
            if (t < 64) {
                float mx = -1e30f;
                #pragma unroll
                for (int j = 0; j < 8; ++j) mx = fmaxf(mx, smem[j * 8 + pc]);
                float sm = 0.0f;
                #pragma unroll
                for (int j = 0; j < 8; ++j) sm += expf(smem[j * 8 + pc] - mx);
                v -= mx + logf(sm);
            }
            __syncthreads();
        }
        if (t < 64) smem[t] = expf(v);
        __syncthreads();

        int id = (blockIdx.x - SINK_BLOCKS) * 512 + t;
        int b  = id >> 7;
        int d4 = id & 127;

        const float4* xb = (const float4*)(x + (size_t)b * DIM) + d4;

        float4 xv[8];
        #pragma unroll
        for (int j = 0; j < 8; ++j) xv[j] = __ldcs(xb + (size_t)j * 128);

        #pragma unroll
        for (int i = 0; i < 8; ++i) {
            float4 acc = make_float4(0.f, 0.f, 0.f, 0.f);
            #pragma unroll
            for (int j = 0; j < 8; ++j) {
                float w = smem[i * 8 + j];
                acc.x += w * xv[j].x;
                acc.y += w * xv[j].y;
                acc.z += w * xv[j].z;
                acc.w += w * xv[j].w;
            }
            __half2 h01 = __floats2half2_rn(acc.x, acc.y);
            __half2 h23 = __floats2half2_rn(acc.z, acc.w);
            size_t e = (size_t)b * DIM + (size_t)i * CSIZE + (size_t)d4 * 4;
            __stcs(((__half2*)yh) + (e >> 1),       h01);
            __stcs(((__half2*)yh) + (e >> 1) + 1,   h23);
        }
    }
}

// ---------------------------------------------------------------------------
// WMMA GEMM, fp16 in / fp32 accum. CTA 128x128, K-step 64, 3-stage ring.
// NEW: 4 warps, warp tile 64x64 (2x2) — halves A-fragment LDSM duplication.
// ncu R16: L1TEX 58.7% > tensor 51.5% -> smem-port-bound (~148 B/cyc demand
// vs 128 B/cyc). 64x64 tiles cut LDSM traffic 96->64 KB/iter (~98 B/cyc).
// ---------------------------------------------------------------------------
#define KSTEP   64
#define NKITER  8                         // 512 / 64
#define NSTAGE  3
#define LDS_PAD 72                        // 64 halfs + 8 pad = 144 B row
#define MAT_ELEMS (128 * LDS_PAD)
#define STAGE_ELEMS (2 * MAT_ELEMS)
#define GEMM_SMEM (NSTAGE * STAGE_ELEMS * 2)   // 110592 bytes

__device__ __forceinline__ void cp16(uint32_t dst, const void* src) {
    asm volatile("cp.async.cg.shared.global [%0], [%1], 16;" :: "r"(dst), "l"(src));
}

__global__ __launch_bounds__(128, 2)
void wmma_gemm_kernel(const __half* __restrict__ yh,
                      const __half* __restrict__ qh,
                      float* __restrict__ out) {
    extern __shared__ __half smem[];

    const int c  = blockIdx.z;
    const int m0 = blockIdx.y * 128;
    const int n0 = blockIdx.x * 128;
    const int tid = threadIdx.x;       // 128 threads, 4 warps
    const int wid = tid >> 5;
    const int wm  = wid & 1;           // 0..1 -> 64-row slab
    const int wn  = wid >> 1;          // 0..1 -> 64-col slab

    wmma::fragment<wmma::accumulator, 16, 16, 16, float> acc[4][4];
    #pragma unroll
    for (int i = 0; i < 4; ++i)
        #pragma unroll
        for (int j = 0; j < 4; ++j) wmma::fill_fragment(acc[i][j], 0.0f);

    // Load assignment per stage: each matrix = 128 rows x 8 x 16B units
    // = 1024 units; 128 threads -> 8 units per thread per matrix.
    int gr[8], gc[8];
    #pragma unroll
    for (int u = 0; u < 8; ++u) {
        int unit = tid + u * 128;
        gr[u] = unit >> 3;          // row 0..127
        gc[u] = unit & 7;           // 16B chunk 0..7
    }
    uint32_t aD[NSTAGE][8], bD[NSTAGE][8];
    #pragma unroll
    for (int s = 0; s < NSTAGE; ++s) {
        __half* sA = smem + s * STAGE_ELEMS;
        __half* sB = sA + MAT_ELEMS;
        #pragma unroll
        for (int u = 0; u < 8; ++u) {
            aD[s][u] = (uint32_t)__cvta_generic_to_shared(
                           sA + gr[u] * LDS_PAD + gc[u] * 8);
            bD[s][u] = (uint32_t)__cvta_generic_to_shared(
                           sB + gr[u] * LDS_PAD + gc[u] * 8);
        }
    }

    const __half* Abase = yh + (size_t)m0 * DIM + (size_t)c * CSIZE;
    const __half* Bbase = qh + (size_t)c * CSIZE * CSIZE + (size_t)n0 * CSIZE;

    auto issue_loads = [&](int i, int st) {
        int kk = i * KSTEP;
        #pragma unroll
        for (int u = 0; u < 8; ++u) {
            cp16(aD[st][u], Abase + (size_t)gr[u] * DIM   + kk + gc[u] * 8);
            cp16(bD[st][u], Bbase + (size_t)gr[u] * CSIZE + kk + gc[u] * 8);
        }
        asm volatile("cp.async.commit_group;" ::: "memory");
    };

    // prologue: 2 stages in flight
    issue_loads(0, 0);
    issue_loads(1, 1);

    for (int i = 0; i < NKITER; ++i) {
        const int st = i % 3;

        if (i + 1 < NKITER)
            asm volatile("cp.async.wait_group 1;" ::: "memory");
        else
            asm volatile("cp.async.wait_group 0;" ::: "memory");
        __syncthreads();   // single barrier per iter; frees stage (i-1)%3

        if (i + 2 < NKITER) issue_loads(i + 2, (i + 2) % 3);

        const __half* As = smem + st * STAGE_ELEMS;
        const __half* Bs = As + MAT_ELEMS;

        #pragma unroll
        for (int k2 = 0; k2 < 4; ++k2) {
            wmma::fragment<wmma::matrix_a, 16, 16, 16, __half, wmma::row_major> af[4];
            wmma::fragment<wmma::matrix_b, 16, 16, 16, __half, wmma::col_major> bf[4];
            #pragma unroll
            for (int mi = 0; mi < 4; ++mi)
                wmma::load_matrix_sync(af[mi],
                    &As[(wm * 64 + mi * 16) * LDS_PAD + k2 * 16], LDS_PAD);
            #pragma unroll
            for (int nj = 0; nj < 4; ++nj)
                wmma::load_matrix_sync(bf[nj],
                    &Bs[(wn * 64 + nj * 16) * LDS_PAD + k2 * 16], LDS_PAD);
            #pragma unroll
            for (int mi = 0; mi < 4; ++mi)
                #pragma unroll
                for (int nj = 0; nj < 4; ++nj)
                    wmma::mma_sync(acc[mi][nj], af[mi], bf[nj], acc[mi][nj]);
        }
        // no trailing barrier: next iter's post-wait sync provides ordering
    }

    // epilogue: direct store to out
    #pragma unroll
    for (int mi = 0; mi < 4; ++mi) {
        #pragma unroll
        for (int nj = 0; nj < 4; ++nj) {
            float* dst = out + (size_t)(m0 + wm * 64 + mi * 16) * DIM
                             + (size_t)c * CSIZE + n0 + wn * 64 + nj * 16;
            wmma::store_matrix_sync(dst, acc[mi][nj], DIM, wmma::mem_row_major);
        }
    }
}

// ---------------------------------------------------------------------------
// Launch: fused (chunk-perm + intra-sinkhorn || mix) -> GEMM.
// ---------------------------------------------------------------------------
extern "C" void kernel_launch(void* const* d_in, const int* in_sizes, int n_in,
                              void* d_out, int out_size) {
    const float* x            = (const float*)d_in[0];
    const float* chunk_logits = (const float*)d_in[1];
    const float* intra_logits = (const float*)d_in[2];
    float*       out          = (float*)d_out;

    float*  rv; cudaGetSymbolAddress((void**)&rv, g_r);
    float*  cv; cudaGetSymbolAddress((void**)&cv, g_c);
    __half* qh; cudaGetSymbolAddress((void**)&qh, g_qh);
    __half* yh; cudaGetSymbolAddress((void**)&yh, g_yh);

    // 1) fused: intra-sinkhorn (64 persistent blocks) || chunk-perm + mix
    fused_pre_kernel<<<SINK_BLOCKS + (NROWS * 128) / 512, 512>>>(
        intra_logits, x, chunk_logits, qh, yh, rv, cv);

    // 2) tensor-core GEMM: 4 warps x (64x64), K-step 64, 3-stage, 2 CTA/SM
    cudaFuncSetAttribute(wmma_gemm_kernel,
                         cudaFuncAttributeMaxDynamicSharedMemorySize, GEMM_SMEM);
    dim3 grid(4, NROWS / 128, CHUNKS);
    wmma_gemm_kernel<<<grid, 128, GEMM_SMEM>>>(yh, qh, out);
}